// round 2
// baseline (speedup 1.0000x reference)
#include <cuda_runtime.h>
#include <math.h>

// Problem constants
#define BATCH 8
#define CIN   96
#define COUT  192
#define NTOK  3136            // 56*56
#define NPOS  (BATCH * NTOK)  // 25088 positions for BN stats

// ---------------- scratch (static device globals; no allocs allowed) -------
__device__ float d_xj[BATCH * CIN * NTOK];     // relu(x - att), channel-major
__device__ float d_y[BATCH * COUT * NTOK];     // pre-BN conv output
__device__ float d_stats[2 * COUT];            // [0:192) sum, [192:384) sumsq

// ============================ attention kernel =============================
// Flash-attention style: per CTA one 64-row block of one batch.
// Q,K,V are all the token matrix x[b] viewed as [N, C] (transpose of storage).
#define BM 64
#define BN 64
#define QPAD 100               // row stride for Qs/Ks (floats), mult of 4
#define ATT_THREADS 256
#define NTILES (NTOK / BN)     // 49

__global__ __launch_bounds__(ATT_THREADS, 2)
void attn_kernel(const float* __restrict__ x, float* __restrict__ xj)
{
    const int b   = blockIdx.y;
    const int n0  = blockIdx.x * BM;
    const int tid = threadIdx.x;
    const int tx  = tid & 15;
    const int ty  = tid >> 4;

    extern __shared__ float sm[];
    float* Qs    = sm;                       // BM * QPAD
    float* Ks    = Qs + BM * QPAD;           // BN * QPAD
    float* Ps    = Ks + BN * QPAD;           // BM * BN
    float* m_sm  = Ps + BM * BN;             // BM
    float* l_sm  = m_sm + BM;                // BM
    float* al_sm = l_sm + BM;                // BM

    const float* xb = x + (size_t)b * CIN * NTOK;

    // load Q block [64 rows x 96 ch]  (Qs[r][c] = x[b][c][n0+r])
    for (int idx = tid; idx < CIN * BM; idx += ATT_THREADS) {
        int c = idx >> 6, r = idx & 63;
        Qs[r * QPAD + c] = xb[c * NTOK + n0 + r];
    }
    if (tid < BM) { m_sm[tid] = -3.0e38f; l_sm[tid] = 0.0f; }

    float o[4][6];
    #pragma unroll
    for (int ii = 0; ii < 4; ++ii)
        #pragma unroll
        for (int cc = 0; cc < 6; ++cc) o[ii][cc] = 0.0f;

    for (int t = 0; t < NTILES; ++t) {
        const int n1 = t * BN;
        __syncthreads();   // Ks (V) reads from previous iteration done
        for (int idx = tid; idx < CIN * BN; idx += ATT_THREADS) {
            int c = idx >> 6, r = idx & 63;
            Ks[r * QPAD + c] = xb[c * NTOK + n1 + r];
        }
        __syncthreads();

        // ---- GEMM1: S = Q_blk * K_tile^T  (4x4 per thread) ----
        float s[4][4];
        #pragma unroll
        for (int ii = 0; ii < 4; ++ii)
            #pragma unroll
            for (int jj = 0; jj < 4; ++jj) s[ii][jj] = 0.0f;

        #pragma unroll 2
        for (int k = 0; k < CIN; k += 4) {
            float4 qa[4], kb[4];
            #pragma unroll
            for (int ii = 0; ii < 4; ++ii)
                qa[ii] = *(const float4*)&Qs[(ty + 16 * ii) * QPAD + k];
            #pragma unroll
            for (int jj = 0; jj < 4; ++jj)
                kb[jj] = *(const float4*)&Ks[(tx + 16 * jj) * QPAD + k];
            #pragma unroll
            for (int ii = 0; ii < 4; ++ii)
                #pragma unroll
                for (int jj = 0; jj < 4; ++jj) {
                    s[ii][jj] = fmaf(qa[ii].x, kb[jj].x, s[ii][jj]);
                    s[ii][jj] = fmaf(qa[ii].y, kb[jj].y, s[ii][jj]);
                    s[ii][jj] = fmaf(qa[ii].z, kb[jj].z, s[ii][jj]);
                    s[ii][jj] = fmaf(qa[ii].w, kb[jj].w, s[ii][jj]);
                }
        }

        // ---- online softmax in register layout (row i spread over 16 lanes) ----
        #pragma unroll
        for (int ii = 0; ii < 4; ++ii) {
            const int i = ty + 16 * ii;
            float mx = fmaxf(fmaxf(s[ii][0], s[ii][1]), fmaxf(s[ii][2], s[ii][3]));
            #pragma unroll
            for (int off = 8; off > 0; off >>= 1)
                mx = fmaxf(mx, __shfl_xor_sync(0xffffffffu, mx, off, 16));
            const float mo = m_sm[i];
            const float mn = fmaxf(mo, mx);
            float rs = 0.0f;
            #pragma unroll
            for (int jj = 0; jj < 4; ++jj) {
                float p = __expf(s[ii][jj] - mn);
                s[ii][jj] = p;
                rs += p;
            }
            #pragma unroll
            for (int off = 8; off > 0; off >>= 1)
                rs += __shfl_xor_sync(0xffffffffu, rs, off, 16);
            if (tx == 0) {
                float al = __expf(mo - mn);
                al_sm[i] = al;
                l_sm[i]  = l_sm[i] * al + rs;
                m_sm[i]  = mn;
            }
            #pragma unroll
            for (int jj = 0; jj < 4; ++jj)
                Ps[i * BN + tx + 16 * jj] = s[ii][jj];
        }
        __syncthreads();

        // ---- rescale O, then GEMM2: O += P * V  (V = Ks) (4x6 per thread) ----
        #pragma unroll
        for (int ii = 0; ii < 4; ++ii) {
            const float al = al_sm[ty + 16 * ii];
            #pragma unroll
            for (int cc = 0; cc < 6; ++cc) o[ii][cc] *= al;
        }
        #pragma unroll 2
        for (int k = 0; k < BN; k += 4) {
            float4 p4[4];
            #pragma unroll
            for (int ii = 0; ii < 4; ++ii)
                p4[ii] = *(const float4*)&Ps[(ty + 16 * ii) * BN + k];
            #pragma unroll
            for (int kk = 0; kk < 4; ++kk) {
                float vb[6];
                #pragma unroll
                for (int cc = 0; cc < 6; ++cc)
                    vb[cc] = Ks[(k + kk) * QPAD + tx + 16 * cc];
                #pragma unroll
                for (int ii = 0; ii < 4; ++ii) {
                    const float pv = ((const float*)&p4[ii])[kk];
                    #pragma unroll
                    for (int cc = 0; cc < 6; ++cc)
                        o[ii][cc] = fmaf(pv, vb[cc], o[ii][cc]);
                }
            }
        }
    }
    __syncthreads();

    // finalize O = acc / l, stage in Ks, then write xj = relu(x - O)
    #pragma unroll
    for (int ii = 0; ii < 4; ++ii) {
        const int i = ty + 16 * ii;
        const float inv = 1.0f / l_sm[i];
        #pragma unroll
        for (int cc = 0; cc < 6; ++cc)
            Ks[i * QPAD + tx + 16 * cc] = o[ii][cc] * inv;
    }
    __syncthreads();

    float* xjb = xj + (size_t)b * CIN * NTOK;
    for (int idx = tid; idx < CIN * BM; idx += ATT_THREADS) {
        int c = idx >> 6, r = idx & 63;
        float v = Qs[r * QPAD + c] - Ks[r * QPAD + c];
        xjb[c * NTOK + n0 + r] = fmaxf(v, 0.0f);
    }
}

// ============================ conv (1x1) kernel ============================
// y[b][o][n] = bias[o] + sum_c W[o][c] * cat[b][c][n]; cat = [x ; xj]
// also accumulates per-channel sum / sumsq for BN.
#define OT 64
#define NT 224
#define KC 32
#define CONV_THREADS 256

__global__ __launch_bounds__(CONV_THREADS, 2)
void conv_kernel(const float* __restrict__ x, const float* __restrict__ xj,
                 const float* __restrict__ w, const float* __restrict__ bias,
                 float* __restrict__ y, float* __restrict__ stats)
{
    const int b  = blockIdx.z;
    const int o0 = blockIdx.y * OT;
    const int nb = blockIdx.x * NT;
    const int tid = threadIdx.x;
    const int tx  = tid & 15;
    const int ty  = tid >> 4;

    extern __shared__ float sm[];
    float* Wsm = sm;             // OT * COUT floats (64*192)
    float* Xsm = Wsm + OT * COUT;// KC * NT floats (32*224)

    // load this CTA's 64 filter rows (full K=192)
    for (int idx = tid; idx < OT * COUT; idx += CONV_THREADS)
        Wsm[idx] = w[(size_t)(o0 + idx / COUT) * COUT + (idx % COUT)];

    float acc[4][14];
    #pragma unroll
    for (int oo = 0; oo < 4; ++oo) {
        const float bv = bias[o0 + ty + 16 * oo];
        #pragma unroll
        for (int nn = 0; nn < 14; ++nn) acc[oo][nn] = bv;
    }

    for (int kc = 0; kc < COUT; kc += KC) {
        __syncthreads();
        for (int idx = tid; idx < KC * NT; idx += CONV_THREADS) {
            const int k = idx / NT, n = idx % NT;
            const int c = kc + k;
            const float* src = (c < CIN)
                ? (x  + ((size_t)b * CIN + c) * NTOK)
                : (xj + ((size_t)b * CIN + (c - CIN)) * NTOK);
            Xsm[k * NT + n] = src[nb + n];
        }
        __syncthreads();
        #pragma unroll 4
        for (int k = 0; k < KC; ++k) {
            float a[4];
            #pragma unroll
            for (int oo = 0; oo < 4; ++oo)
                a[oo] = Wsm[(ty + 16 * oo) * COUT + kc + k];
            float bx[14];
            #pragma unroll
            for (int nn = 0; nn < 14; ++nn)
                bx[nn] = Xsm[k * NT + tx + 16 * nn];
            #pragma unroll
            for (int oo = 0; oo < 4; ++oo)
                #pragma unroll
                for (int nn = 0; nn < 14; ++nn)
                    acc[oo][nn] = fmaf(a[oo], bx[nn], acc[oo][nn]);
        }
    }

    // store + per-channel partial stats
    float* yb = y + ((size_t)b * COUT + o0) * NTOK + nb;
    #pragma unroll
    for (int oo = 0; oo < 4; ++oo) {
        const int o = ty + 16 * oo;
        float s1 = 0.0f, s2 = 0.0f;
        #pragma unroll
        for (int nn = 0; nn < 14; ++nn) {
            const float v = acc[oo][nn];
            yb[(size_t)o * NTOK + tx + 16 * nn] = v;
            s1 += v;
            s2 += v * v;
        }
        #pragma unroll
        for (int off = 8; off > 0; off >>= 1) {
            s1 += __shfl_xor_sync(0xffffffffu, s1, off, 16);
            s2 += __shfl_xor_sync(0xffffffffu, s2, off, 16);
        }
        if (tx == 0) {
            atomicAdd(&stats[o0 + o], s1);
            atomicAdd(&stats[COUT + o0 + o], s2);
        }
    }
}

// ============================ BN + GELU kernel =============================
__global__ void bn_gelu_kernel(const float* __restrict__ y,
                               const float* __restrict__ stats,
                               const float* __restrict__ gamma,
                               const float* __restrict__ beta,
                               float* __restrict__ out)
{
    const size_t idx = (size_t)blockIdx.x * blockDim.x + threadIdx.x;
    const int o = (int)((idx / NTOK) % COUT);
    const float invN = 1.0f / (float)NPOS;
    const float mean = stats[o] * invN;
    const float var  = stats[COUT + o] * invN - mean * mean;
    const float sc   = rsqrtf(var + 1e-5f);
    float v = (y[idx] - mean) * sc * gamma[o] + beta[o];
    out[idx] = 0.5f * v * (1.0f + erff(v * 0.70710678118654752f));
}

__global__ void zero_stats_kernel(float* stats)
{
    stats[threadIdx.x] = 0.0f;
}

// ================================ launch ===================================
extern "C" void kernel_launch(void* const* d_in, const int* in_sizes, int n_in,
                              void* d_out, int out_size)
{
    const float* x      = (const float*)d_in[0];
    const float* conv_w = (const float*)d_in[1];
    const float* conv_b = (const float*)d_in[2];
    const float* gamma  = (const float*)d_in[3];
    const float* beta   = (const float*)d_in[4];
    float* out = (float*)d_out;

    float *xj, *y, *stats;
    cudaGetSymbolAddress((void**)&xj, d_xj);
    cudaGetSymbolAddress((void**)&y, d_y);
    cudaGetSymbolAddress((void**)&stats, d_stats);

    const int attn_smem = (BM * QPAD + BN * QPAD + BM * BN + 3 * BM) * (int)sizeof(float);
    const int conv_smem = (OT * COUT + KC * NT) * (int)sizeof(float);
    cudaFuncSetAttribute(attn_kernel, cudaFuncAttributeMaxDynamicSharedMemorySize, attn_smem);
    cudaFuncSetAttribute(conv_kernel, cudaFuncAttributeMaxDynamicSharedMemorySize, conv_smem);

    zero_stats_kernel<<<1, 2 * COUT>>>(stats);

    dim3 agrid(NTOK / BM, BATCH);
    attn_kernel<<<agrid, ATT_THREADS, attn_smem>>>(x, xj);

    dim3 cgrid(NTOK / NT, COUT / OT, BATCH);
    conv_kernel<<<cgrid, CONV_THREADS, conv_smem>>>(x, xj, conv_w, conv_b, y, stats);

    const size_t total = (size_t)BATCH * COUT * NTOK;
    bn_gelu_kernel<<<(unsigned)(total / 256), 256>>>(y, stats, gamma, beta, out);
}

// round 4
// speedup vs baseline: 1.7271x; 1.7271x over previous
#include <cuda_runtime.h>
#include <cuda_bf16.h>
#include <cstdint>
#include <math.h>

#define BATCH 8
#define CIN   96
#define COUT  192
#define NTOK  3136
#define NPOS  (BATCH * NTOK)

__device__ float d_xj[BATCH * CIN * NTOK];
__device__ float d_y[BATCH * COUT * NTOK];
__device__ float d_stats[2 * COUT];

// ---------------- helpers ----------------
__device__ __forceinline__ uint32_t smem_u32(const void* p){
    uint32_t a;
    asm("{ .reg .u64 t; cvta.to.shared.u64 t, %1; cvt.u32.u64 %0, t; }" : "=r"(a) : "l"(p));
    return a;
}
__device__ __forceinline__ void ldsm4(uint32_t* r, uint32_t addr){
    asm volatile("ldmatrix.sync.aligned.m8n8.x4.shared.b16 {%0,%1,%2,%3}, [%4];"
        : "=r"(r[0]), "=r"(r[1]), "=r"(r[2]), "=r"(r[3]) : "r"(addr));
}
__device__ __forceinline__ void mma16816(float* d, const uint32_t* a, uint32_t b0, uint32_t b1){
    asm volatile("mma.sync.aligned.m16n8k16.row.col.f32.bf16.bf16.f32 "
        "{%0,%1,%2,%3}, {%4,%5,%6,%7}, {%8,%9}, {%0,%1,%2,%3};"
        : "+f"(d[0]), "+f"(d[1]), "+f"(d[2]), "+f"(d[3])
        : "r"(a[0]), "r"(a[1]), "r"(a[2]), "r"(a[3]), "r"(b0), "r"(b1));
}
__device__ __forceinline__ void split2(float f, __nv_bfloat16& h, __nv_bfloat16& lo){
    h  = __float2bfloat16(f);
    lo = __float2bfloat16(f - __bfloat162float(h));
}
__device__ __forceinline__ uint32_t packp(float a, float b){
    __nv_bfloat162 h = __floats2bfloat162_rn(a, b);
    return *reinterpret_cast<uint32_t*>(&h);
}

// ---------------- attention (mma.sync bf16 split) ----------------
// smem byte layout:
//   Qhi [128][104] bf16 @ 0        (26624)
//   Qlo [128][104] bf16 @ 26624    (26624)
//   buf b @ 53248 + b*54272:
//     Khi [64][104] @ +0, Klo @ +13312, Vhi [96][72] @ +26624, Vlo @ +40448
#define O_QHI 0
#define O_QLO 26624
#define O_BUF 53248
#define BUFSZ 54272
#define ATT_SMEM 161792
#define NKT 49
#define NQB 25

__device__ __forceinline__ void kv_stage(char* sm, uint32_t bufoff, const float* xb, int t){
    const int n1 = t * 64;
    for (int idx = threadIdx.x; idx < 64 * 96; idx += 256){
        const int tok = idx & 63, c = idx >> 6;
        __nv_bfloat16 h, lo;
        split2(xb[c * NTOK + n1 + tok], h, lo);
        *(__nv_bfloat16*)(sm + bufoff +          (tok * 104 + c) * 2) = h;
        *(__nv_bfloat16*)(sm + bufoff + 13312 +  (tok * 104 + c) * 2) = lo;
        *(__nv_bfloat16*)(sm + bufoff + 26624 +  (c * 72 + tok) * 2) = h;
        *(__nv_bfloat16*)(sm + bufoff + 40448 +  (c * 72 + tok) * 2) = lo;
    }
}

__global__ __launch_bounds__(256, 1)
void attn_mma(const float* __restrict__ x, float* __restrict__ xj)
{
    extern __shared__ char sm[];
    const int tid = threadIdx.x, w = tid >> 5, ln = tid & 31;
    const int b = blockIdx.y, n0 = blockIdx.x * 128;
    const float* xb = x + (size_t)b * CIN * NTOK;
    const uint32_t smb = smem_u32(sm);

    // stage Q (hi/lo), zero-pad invalid rows
    for (int idx = tid; idx < 128 * 96; idx += 256){
        const int r = idx & 127, c = idx >> 7;
        const int nq = n0 + r;
        const float f = (nq < NTOK) ? xb[c * NTOK + nq] : 0.0f;
        __nv_bfloat16 h, lo;
        split2(f, h, lo);
        *(__nv_bfloat16*)(sm + O_QHI + (r * 104 + c) * 2) = h;
        *(__nv_bfloat16*)(sm + O_QLO + (r * 104 + c) * 2) = lo;
    }
    kv_stage(sm, O_BUF, xb, 0);
    __syncthreads();

    // M_i = ||q_i||^2 for this thread's two accumulator rows
    const int r0 = 16 * w + (ln >> 2), r1 = r0 + 8;
    float M0 = 0.0f, M1 = 0.0f;
    {
        const int c0 = (ln & 3) * 24;
        #pragma unroll 8
        for (int i = 0; i < 24; ++i){
            const int c = c0 + i;
            float q0 = __bfloat162float(*(__nv_bfloat16*)(sm + O_QHI + (r0 * 104 + c) * 2))
                     + __bfloat162float(*(__nv_bfloat16*)(sm + O_QLO + (r0 * 104 + c) * 2));
            float q1 = __bfloat162float(*(__nv_bfloat16*)(sm + O_QHI + (r1 * 104 + c) * 2))
                     + __bfloat162float(*(__nv_bfloat16*)(sm + O_QLO + (r1 * 104 + c) * 2));
            M0 = fmaf(q0, q0, M0);
            M1 = fmaf(q1, q1, M1);
        }
        M0 += __shfl_xor_sync(0xffffffffu, M0, 1);
        M0 += __shfl_xor_sync(0xffffffffu, M0, 2);
        M1 += __shfl_xor_sync(0xffffffffu, M1, 1);
        M1 += __shfl_xor_sync(0xffffffffu, M1, 2);
    }

    // ldmatrix per-lane address pattern
    const int arow = ((ln >> 3) & 1) * 8 + (ln & 7);
    const int acol = (ln >> 4) * 8;

    // preload Q fragments (held across all tiles)
    uint32_t Qh[6][4], Ql[6][4];
    {
        const uint32_t aq = smb + (uint32_t)((16 * w + arow) * 208 + acol * 2);
        #pragma unroll
        for (int kk = 0; kk < 6; ++kk){
            ldsm4(Qh[kk], aq + O_QHI + kk * 32);
            ldsm4(Ql[kk], aq + O_QLO + kk * 32);
        }
    }

    float O[12][4];
    #pragma unroll
    for (int n = 0; n < 12; ++n){ O[n][0]=0.f; O[n][1]=0.f; O[n][2]=0.f; O[n][3]=0.f; }
    float L0 = 0.0f, L1 = 0.0f;

    for (int t = 0; t < NKT; ++t){
        const uint32_t cb = O_BUF + (uint32_t)(t & 1) * BUFSZ;
        if (t + 1 < NKT) kv_stage(sm, O_BUF + (uint32_t)((t + 1) & 1) * BUFSZ, xb, t + 1);

        // ---- GEMM1: S = Q K^T (3 passes) ----
        float S[8][4];
        #pragma unroll
        for (int n = 0; n < 8; ++n){ S[n][0]=0.f; S[n][1]=0.f; S[n][2]=0.f; S[n][3]=0.f; }

        #pragma unroll
        for (int pass = 0; pass < 3; ++pass){
            const uint32_t (*A)[4] = (pass == 2) ? Ql : Qh;
            const uint32_t kb = smb + cb + ((pass == 1) ? 13312u : 0u)
                              + (uint32_t)(arow * 208 + acol * 2);
            #pragma unroll
            for (int kk = 0; kk < 6; ++kk){
                #pragma unroll
                for (int g = 0; g < 4; ++g){
                    uint32_t bb[4];
                    ldsm4(bb, kb + (uint32_t)(g * 16 * 208 + kk * 32));
                    mma16816(S[2 * g],     A[kk], bb[0], bb[2]);
                    mma16816(S[2 * g + 1], A[kk], bb[1], bb[3]);
                }
            }
        }

        // ---- softmax: P = exp(S - M), accumulate L, repack as A-fragments ----
        uint32_t Ph[4][4], Pl[4][4];
        #pragma unroll
        for (int n = 0; n < 8; ++n){
            const float p0 = __expf(S[n][0] - M0);
            const float p1 = __expf(S[n][1] - M0);
            const float p2 = __expf(S[n][2] - M1);
            const float p3 = __expf(S[n][3] - M1);
            L0 += p0 + p1;
            L1 += p2 + p3;
            const int kt = n >> 1, hh = (n & 1) * 2;
            Ph[kt][hh]     = packp(p0, p1);
            Ph[kt][hh + 1] = packp(p2, p3);
            const float q0 = p0 - __bfloat162float(__float2bfloat16(p0));
            const float q1 = p1 - __bfloat162float(__float2bfloat16(p1));
            const float q2 = p2 - __bfloat162float(__float2bfloat16(p2));
            const float q3 = p3 - __bfloat162float(__float2bfloat16(p3));
            Pl[kt][hh]     = packp(q0, q1);
            Pl[kt][hh + 1] = packp(q2, q3);
        }

        // ---- GEMM2: O += P V (3 passes) ----
        #pragma unroll
        for (int pass = 0; pass < 3; ++pass){
            const uint32_t (*A)[4] = (pass == 2) ? Pl : Ph;
            const uint32_t vb = smb + cb + 26624u + ((pass == 1) ? 13824u : 0u)
                              + (uint32_t)(arow * 144 + acol * 2);
            #pragma unroll
            for (int kt = 0; kt < 4; ++kt){
                #pragma unroll
                for (int g = 0; g < 6; ++g){
                    uint32_t bb[4];
                    ldsm4(bb, vb + (uint32_t)(g * 16 * 144 + kt * 32));
                    mma16816(O[2 * g],     A[kt], bb[0], bb[2]);
                    mma16816(O[2 * g + 1], A[kt], bb[1], bb[3]);
                }
            }
        }
        __syncthreads();
    }

    // reduce L across the quad (lanes sharing a row)
    L0 += __shfl_xor_sync(0xffffffffu, L0, 1);
    L0 += __shfl_xor_sync(0xffffffffu, L0, 2);
    L1 += __shfl_xor_sync(0xffffffffu, L1, 1);
    L1 += __shfl_xor_sync(0xffffffffu, L1, 2);
    const float inv0 = 1.0f / L0, inv1 = 1.0f / L1;

    // stage O/l into smem as [ch][tok] f32 (stride 132), then write xj coalesced
    float* Ost = (float*)(sm + O_BUF);
    #pragma unroll
    for (int n = 0; n < 12; ++n){
        const int c = 8 * n + 2 * (ln & 3);
        Ost[c * 132 + r0]       = O[n][0] * inv0;
        Ost[(c + 1) * 132 + r0] = O[n][1] * inv0;
        Ost[c * 132 + r1]       = O[n][2] * inv1;
        Ost[(c + 1) * 132 + r1] = O[n][3] * inv1;
    }
    __syncthreads();

    float* xjb = xj + (size_t)b * CIN * NTOK;
    for (int idx = tid; idx < 96 * 128; idx += 256){
        const int tok = idx & 127, c = idx >> 7;
        const int nq = n0 + tok;
        if (nq < NTOK){
            const float v = xb[c * NTOK + nq] - Ost[c * 132 + tok];
            xjb[(size_t)c * NTOK + nq] = fmaxf(v, 0.0f);
        }
    }
}

// ---------------- conv 1x1 + BN stats ----------------
#define OT 64
#define NT 224
#define KC 32
__global__ __launch_bounds__(256, 2)
void conv_kernel(const float* __restrict__ x, const float* __restrict__ xj,
                 const float* __restrict__ w, const float* __restrict__ bias,
                 float* __restrict__ y, float* __restrict__ stats)
{
    const int b = blockIdx.z, o0 = blockIdx.y * OT, nb = blockIdx.x * NT;
    const int tid = threadIdx.x, tx = tid & 15, ty = tid >> 4;
    extern __shared__ float smf[];
    float* Wsm = smf;
    float* Xsm = Wsm + OT * COUT;

    for (int idx = tid; idx < OT * COUT; idx += 256)
        Wsm[idx] = w[(size_t)(o0 + idx / COUT) * COUT + (idx % COUT)];

    float acc[4][14];
    #pragma unroll
    for (int oo = 0; oo < 4; ++oo){
        const float bv = bias[o0 + ty + 16 * oo];
        #pragma unroll
        for (int nn = 0; nn < 14; ++nn) acc[oo][nn] = bv;
    }
    for (int kc = 0; kc < COUT; kc += KC){
        __syncthreads();
        for (int idx = tid; idx < KC * NT; idx += 256){
            const int k = idx / NT, n = idx % NT, c = kc + k;
            const float* src = (c < CIN) ? (x + ((size_t)b * CIN + c) * NTOK)
                                         : (xj + ((size_t)b * CIN + (c - CIN)) * NTOK);
            Xsm[k * NT + n] = src[nb + n];
        }
        __syncthreads();
        #pragma unroll 4
        for (int k = 0; k < KC; ++k){
            float a[4];
            #pragma unroll
            for (int oo = 0; oo < 4; ++oo) a[oo] = Wsm[(ty + 16 * oo) * COUT + kc + k];
            float bx[14];
            #pragma unroll
            for (int nn = 0; nn < 14; ++nn) bx[nn] = Xsm[k * NT + tx + 16 * nn];
            #pragma unroll
            for (int oo = 0; oo < 4; ++oo)
                #pragma unroll
                for (int nn = 0; nn < 14; ++nn)
                    acc[oo][nn] = fmaf(a[oo], bx[nn], acc[oo][nn]);
        }
    }
    float* yb = y + ((size_t)b * COUT + o0) * NTOK + nb;
    #pragma unroll
    for (int oo = 0; oo < 4; ++oo){
        const int o = ty + 16 * oo;
        float s1 = 0.0f, s2 = 0.0f;
        #pragma unroll
        for (int nn = 0; nn < 14; ++nn){
            const float v = acc[oo][nn];
            yb[(size_t)o * NTOK + tx + 16 * nn] = v;
            s1 += v; s2 += v * v;
        }
        #pragma unroll
        for (int off = 8; off > 0; off >>= 1){
            s1 += __shfl_xor_sync(0xffffffffu, s1, off, 16);
            s2 += __shfl_xor_sync(0xffffffffu, s2, off, 16);
        }
        if (tx == 0){ atomicAdd(&stats[o0 + o], s1); atomicAdd(&stats[COUT + o0 + o], s2); }
    }
}

__global__ void bn_gelu_kernel(const float* __restrict__ y, const float* __restrict__ stats,
                               const float* __restrict__ gamma, const float* __restrict__ beta,
                               float* __restrict__ out)
{
    const size_t idx = (size_t)blockIdx.x * blockDim.x + threadIdx.x;
    const int o = (int)((idx / NTOK) % COUT);
    const float invN = 1.0f / (float)NPOS;
    const float mean = stats[o] * invN;
    const float var  = stats[COUT + o] * invN - mean * mean;
    const float sc   = rsqrtf(var + 1e-5f);
    float v = (y[idx] - mean) * sc * gamma[o] + beta[o];
    out[idx] = 0.5f * v * (1.0f + erff(v * 0.70710678118654752f));
}

__global__ void zero_stats_kernel(float* stats){ stats[threadIdx.x] = 0.0f; }

// ---------------- launch ----------------
extern "C" void kernel_launch(void* const* d_in, const int* in_sizes, int n_in,
                              void* d_out, int out_size)
{
    const float* x      = (const float*)d_in[0];
    const float* conv_w = (const float*)d_in[1];
    const float* conv_b = (const float*)d_in[2];
    const float* gamma  = (const float*)d_in[3];
    const float* beta   = (const float*)d_in[4];
    float* out = (float*)d_out;

    float *xj, *y, *stats;
    cudaGetSymbolAddress((void**)&xj, d_xj);
    cudaGetSymbolAddress((void**)&y, d_y);
    cudaGetSymbolAddress((void**)&stats, d_stats);

    const int conv_smem = (OT * COUT + KC * NT) * (int)sizeof(float);
    cudaFuncSetAttribute(attn_mma, cudaFuncAttributeMaxDynamicSharedMemorySize, ATT_SMEM);
    cudaFuncSetAttribute(conv_kernel, cudaFuncAttributeMaxDynamicSharedMemorySize, conv_smem);

    zero_stats_kernel<<<1, 2 * COUT>>>(stats);

    dim3 agrid(NQB, BATCH);
    attn_mma<<<agrid, 256, ATT_SMEM>>>(x, xj);

    dim3 cgrid(NTOK / NT, COUT / OT, BATCH);
    conv_kernel<<<cgrid, 256, conv_smem>>>(x, xj, conv_w, conv_b, y, stats);

    const size_t total = (size_t)BATCH * COUT * NTOK;
    bn_gelu_kernel<<<(unsigned)(total / 256), 256>>>(y, stats, gamma, beta, out);
}

// round 5
// speedup vs baseline: 3.7927x; 2.1960x over previous
#include <cuda_runtime.h>
#include <cuda_bf16.h>
#include <cstdint>
#include <math.h>

#define BATCH 8
#define CIN   96
#define COUT  192
#define NTOK  3136
#define NPOS  (BATCH * NTOK)
#define NPAD  3200            // padded token rows for kT

__device__ float d_xj[BATCH * CIN * NTOK];
__device__ float d_y[BATCH * COUT * NTOK];
__device__ float d_stats[2 * COUT];
__device__ __nv_bfloat16 d_kThi[BATCH * NPAD * CIN];   // [b][tok][c]
__device__ __nv_bfloat16 d_kTlo[BATCH * NPAD * CIN];
__device__ __nv_bfloat16 d_vhi[BATCH * CIN * NTOK];    // [b][c][tok]
__device__ __nv_bfloat16 d_vlo[BATCH * CIN * NTOK];
__device__ float d_m[BATCH * NTOK];

// ---------------- helpers ----------------
__device__ __forceinline__ uint32_t smem_u32(const void* p){
    uint32_t a;
    asm("{ .reg .u64 t; cvta.to.shared.u64 t, %1; cvt.u32.u64 %0, t; }" : "=r"(a) : "l"(p));
    return a;
}
__device__ __forceinline__ void ldsm4(uint32_t* r, uint32_t addr){
    asm volatile("ldmatrix.sync.aligned.m8n8.x4.shared.b16 {%0,%1,%2,%3}, [%4];"
        : "=r"(r[0]), "=r"(r[1]), "=r"(r[2]), "=r"(r[3]) : "r"(addr));
}
__device__ __forceinline__ void mma16816(float* d, const uint32_t* a, uint32_t b0, uint32_t b1){
    asm volatile("mma.sync.aligned.m16n8k16.row.col.f32.bf16.bf16.f32 "
        "{%0,%1,%2,%3}, {%4,%5,%6,%7}, {%8,%9}, {%0,%1,%2,%3};"
        : "+f"(d[0]), "+f"(d[1]), "+f"(d[2]), "+f"(d[3])
        : "r"(a[0]), "r"(a[1]), "r"(a[2]), "r"(a[3]), "r"(b0), "r"(b1));
}
__device__ __forceinline__ void split2(float f, __nv_bfloat16& h, __nv_bfloat16& lo){
    h  = __float2bfloat16(f);
    lo = __float2bfloat16(f - __bfloat162float(h));
}
__device__ __forceinline__ uint32_t packp(float a, float b){
    __nv_bfloat162 h = __floats2bfloat162_rn(a, b);
    return *reinterpret_cast<uint32_t*>(&h);
}
__device__ __forceinline__ void cpa16(uint32_t s, const void* g){
    unsigned long long ga = __cvta_generic_to_global(g);
    asm volatile("cp.async.cg.shared.global [%0], [%1], 16;" :: "r"(s), "l"(ga));
}
__device__ __forceinline__ void cpa_commit(){ asm volatile("cp.async.commit_group;"); }

// ---------------- prep kernels ----------------
__global__ void prep_kT(const float* __restrict__ x,
                        __nv_bfloat16* __restrict__ kThi, __nv_bfloat16* __restrict__ kTlo)
{
    __shared__ float tile[32][33];
    const int n0 = blockIdx.x * 32, c0 = blockIdx.y * 32, b = blockIdx.z;
    const float* xb = x + (size_t)b * CIN * NTOK;
    const int lane = threadIdx.x & 31, grp = threadIdx.x >> 5;
    #pragma unroll
    for (int i = 0; i < 4; ++i){
        const int c = i * 8 + grp, n = n0 + lane;
        tile[c][lane] = (n < NTOK) ? xb[(size_t)(c0 + c) * NTOK + n] : 0.0f;
    }
    __syncthreads();
    #pragma unroll
    for (int i = 0; i < 4; ++i){
        const int tok = i * 8 + grp, c = lane;
        __nv_bfloat16 h, lo;
        split2(tile[c][tok], h, lo);
        const size_t o = ((size_t)b * NPAD + n0 + tok) * CIN + c0 + c;
        kThi[o] = h; kTlo[o] = lo;
    }
}

__global__ void prep_v(const float* __restrict__ x,
                       __nv_bfloat16* __restrict__ vhi, __nv_bfloat16* __restrict__ vlo)
{
    const size_t i = (size_t)blockIdx.x * blockDim.x + threadIdx.x;
    __nv_bfloat16 h, lo;
    split2(x[i], h, lo);
    vhi[i] = h; vlo[i] = lo;
}

__global__ void prep_m(const float* __restrict__ x, float* __restrict__ m)
{
    const int n = blockIdx.x * 256 + threadIdx.x;
    const int b = blockIdx.y;
    if (n < NTOK){
        const float* xb = x + (size_t)b * CIN * NTOK + n;
        float s = 0.0f;
        #pragma unroll 8
        for (int c = 0; c < CIN; ++c){ float f = xb[(size_t)c * NTOK]; s = fmaf(f, f, s); }
        m[b * NTOK + n] = s;
    }
}

// ---------------- attention ----------------
#define O_QHI 0
#define O_QLO 26624
#define O_BUF 53248
#define BUFSZ 54272
#define ATT_SMEM 161792
#define NKT 49
#define NQB 25

__device__ __forceinline__ void issue_kv(uint32_t smb, int buf,
    const char* kThi, const char* kTlo, const char* vhi, const char* vlo, int t)
{
    const uint32_t base = smb + O_BUF + (uint32_t)buf * BUFSZ;
    const int n1 = t * 64;
    #pragma unroll
    for (int i = 0; i < 3; ++i){
        const int q = threadIdx.x + i * 256;
        const int row = q / 12, cbk = q % 12;
        cpa16(base + row * 208 + cbk * 16,          kThi + (size_t)(n1 + row) * 192 + cbk * 16);
        cpa16(base + 13312 + row * 208 + cbk * 16,  kTlo + (size_t)(n1 + row) * 192 + cbk * 16);
        const int c = q >> 3, cbv = q & 7;
        cpa16(base + 26624 + c * 144 + cbv * 16,    vhi + ((size_t)c * NTOK + n1) * 2 + cbv * 16);
        cpa16(base + 40448 + c * 144 + cbv * 16,    vlo + ((size_t)c * NTOK + n1) * 2 + cbv * 16);
    }
}

__device__ __forceinline__ void gemm1_pass(float S[8][4], const uint32_t A[6][4], uint32_t kb){
    #pragma unroll
    for (int kk = 0; kk < 6; ++kk){
        #pragma unroll
        for (int g = 0; g < 4; ++g){
            uint32_t bb[4];
            ldsm4(bb, kb + (uint32_t)(g * 16 * 208 + kk * 32));
            mma16816(S[2 * g],     A[kk], bb[0], bb[2]);
            mma16816(S[2 * g + 1], A[kk], bb[1], bb[3]);
        }
    }
}
__device__ __forceinline__ void gemm2_pass(float O[12][4], const uint32_t A[4][4], uint32_t vb){
    #pragma unroll
    for (int kt = 0; kt < 4; ++kt){
        #pragma unroll
        for (int g = 0; g < 6; ++g){
            uint32_t bb[4];
            ldsm4(bb, vb + (uint32_t)(g * 16 * 144 + kt * 32));
            mma16816(O[2 * g],     A[kt], bb[0], bb[2]);
            mma16816(O[2 * g + 1], A[kt], bb[1], bb[3]);
        }
    }
}

__global__ __launch_bounds__(256, 1)
void attn_mma(const float* __restrict__ x, float* __restrict__ xj,
              const __nv_bfloat16* __restrict__ kThi_g, const __nv_bfloat16* __restrict__ kTlo_g,
              const __nv_bfloat16* __restrict__ vhi_g, const __nv_bfloat16* __restrict__ vlo_g,
              const float* __restrict__ m_g)
{
    extern __shared__ char sm[];
    const int tid = threadIdx.x, w = tid >> 5, ln = tid & 31;
    const int b = blockIdx.y, n0 = blockIdx.x * 128;
    const uint32_t smb = smem_u32(sm);
    const char* kThi = (const char*)(kThi_g + (size_t)b * NPAD * CIN);
    const char* kTlo = (const char*)(kTlo_g + (size_t)b * NPAD * CIN);
    const char* vhi  = (const char*)(vhi_g + (size_t)b * CIN * NTOK);
    const char* vlo  = (const char*)(vlo_g + (size_t)b * CIN * NTOK);

    // group0: Q tile (hi+lo) via cp.async from kT (padded rows are zeros)
    #pragma unroll
    for (int i = 0; i < 6; ++i){
        const int q = tid + i * 256;
        const int row = q / 12, cb = q % 12;
        cpa16(smb + O_QHI + row * 208 + cb * 16, kThi + (size_t)(n0 + row) * 192 + cb * 16);
        cpa16(smb + O_QLO + row * 208 + cb * 16, kTlo + (size_t)(n0 + row) * 192 + cb * 16);
    }
    cpa_commit();
    // group1: KV tile 0
    issue_kv(smb, 0, kThi, kTlo, vhi, vlo, 0);
    cpa_commit();

    // per-thread row constants
    const int r0 = 16 * w + (ln >> 2), r1 = r0 + 8;
    const float M0 = (n0 + r0 < NTOK) ? m_g[b * NTOK + n0 + r0] : 3.0e38f;
    const float M1 = (n0 + r1 < NTOK) ? m_g[b * NTOK + n0 + r1] : 3.0e38f;

    asm volatile("cp.async.wait_group 1;" ::: "memory");   // Q ready
    __syncthreads();

    const int arow = ((ln >> 3) & 1) * 8 + (ln & 7);
    const int acol = (ln >> 4) * 8;
    uint32_t Qh[6][4], Ql[6][4];
    {
        const uint32_t aq = smb + (uint32_t)((16 * w + arow) * 208 + acol * 2);
        #pragma unroll
        for (int kk = 0; kk < 6; ++kk){
            ldsm4(Qh[kk], aq + O_QHI + kk * 32);
            ldsm4(Ql[kk], aq + O_QLO + kk * 32);
        }
    }

    float O[12][4];
    #pragma unroll
    for (int n = 0; n < 12; ++n){ O[n][0]=0.f; O[n][1]=0.f; O[n][2]=0.f; O[n][3]=0.f; }
    float L0 = 0.0f, L1 = 0.0f;

    for (int t = 0; t < NKT; ++t){
        if (t + 1 < NKT){
            issue_kv(smb, (t + 1) & 1, kThi, kTlo, vhi, vlo, t + 1);
            cpa_commit();
            asm volatile("cp.async.wait_group 1;" ::: "memory");
        } else {
            asm volatile("cp.async.wait_group 0;" ::: "memory");
        }
        __syncthreads();

        const uint32_t cb = O_BUF + (uint32_t)(t & 1) * BUFSZ;
        const uint32_t kb_hi = smb + cb + (uint32_t)(arow * 208 + acol * 2);

        // GEMM1 hh pass
        float S[8][4];
        #pragma unroll
        for (int n = 0; n < 8; ++n){ S[n][0]=0.f; S[n][1]=0.f; S[n][2]=0.f; S[n][3]=0.f; }
        gemm1_pass(S, Qh, kb_hi);

        // per-warp significance vote
        float mx = -3.0e38f;
        #pragma unroll
        for (int n = 0; n < 8; ++n){
            mx = fmaxf(mx, fmaxf(S[n][0], S[n][1]) - M0);
            mx = fmaxf(mx, fmaxf(S[n][2], S[n][3]) - M1);
        }
        const uint32_t need = __ballot_sync(0xffffffffu, mx >= -19.0f);

        if (need){
            // finish GEMM1: hi*lo + lo*hi
            gemm1_pass(S, Qh, kb_hi + 13312u);
            gemm1_pass(S, Ql, kb_hi);

            // softmax: P = exp(S - M), accumulate L, repack as A-fragments
            uint32_t Ph[4][4], Pl[4][4];
            #pragma unroll
            for (int n = 0; n < 8; ++n){
                const float p0 = __expf(S[n][0] - M0);
                const float p1 = __expf(S[n][1] - M0);
                const float p2 = __expf(S[n][2] - M1);
                const float p3 = __expf(S[n][3] - M1);
                L0 += p0 + p1;
                L1 += p2 + p3;
                const int kt = n >> 1, hh = (n & 1) * 2;
                Ph[kt][hh]     = packp(p0, p1);
                Ph[kt][hh + 1] = packp(p2, p3);
                const float q0 = p0 - __bfloat162float(__float2bfloat16(p0));
                const float q1 = p1 - __bfloat162float(__float2bfloat16(p1));
                const float q2 = p2 - __bfloat162float(__float2bfloat16(p2));
                const float q3 = p3 - __bfloat162float(__float2bfloat16(p3));
                Pl[kt][hh]     = packp(q0, q1);
                Pl[kt][hh + 1] = packp(q2, q3);
            }

            // GEMM2: O += P V (3 passes)
            const uint32_t vb = smb + cb + 26624u + (uint32_t)(arow * 144 + acol * 2);
            gemm2_pass(O, Ph, vb);
            gemm2_pass(O, Ph, vb + 13824u);
            gemm2_pass(O, Pl, vb);
        }
        __syncthreads();
    }

    L0 += __shfl_xor_sync(0xffffffffu, L0, 1);
    L0 += __shfl_xor_sync(0xffffffffu, L0, 2);
    L1 += __shfl_xor_sync(0xffffffffu, L1, 1);
    L1 += __shfl_xor_sync(0xffffffffu, L1, 2);
    const float inv0 = 1.0f / L0, inv1 = 1.0f / L1;

    float* Ost = (float*)(sm + O_BUF);
    #pragma unroll
    for (int n = 0; n < 12; ++n){
        const int c = 8 * n + 2 * (ln & 3);
        Ost[c * 132 + r0]       = O[n][0] * inv0;
        Ost[(c + 1) * 132 + r0] = O[n][1] * inv0;
        Ost[c * 132 + r1]       = O[n][2] * inv1;
        Ost[(c + 1) * 132 + r1] = O[n][3] * inv1;
    }
    __syncthreads();

    const float* xb = x + (size_t)b * CIN * NTOK;
    float* xjb = xj + (size_t)b * CIN * NTOK;
    for (int idx = tid; idx < 96 * 128; idx += 256){
        const int tok = idx & 127, c = idx >> 7;
        const int nq = n0 + tok;
        if (nq < NTOK){
            const float v = xb[(size_t)c * NTOK + nq] - Ost[c * 132 + tok];
            xjb[(size_t)c * NTOK + nq] = fmaxf(v, 0.0f);
        }
    }
}

// ---------------- conv 1x1 + BN stats ----------------
#define OT 64
#define NT 224
#define KC 32
__global__ __launch_bounds__(256, 2)
void conv_kernel(const float* __restrict__ x, const float* __restrict__ xj,
                 const float* __restrict__ w, const float* __restrict__ bias,
                 float* __restrict__ y, float* __restrict__ stats)
{
    const int b = blockIdx.z, o0 = blockIdx.y * OT, nb = blockIdx.x * NT;
    const int tid = threadIdx.x, tx = tid & 15, ty = tid >> 4;
    extern __shared__ float smf[];
    float* Wsm = smf;
    float* Xsm = Wsm + OT * COUT;

    for (int idx = tid; idx < OT * COUT; idx += 256)
        Wsm[idx] = w[(size_t)(o0 + idx / COUT) * COUT + (idx % COUT)];

    float acc[4][14];
    #pragma unroll
    for (int oo = 0; oo < 4; ++oo){
        const float bv = bias[o0 + ty + 16 * oo];
        #pragma unroll
        for (int nn = 0; nn < 14; ++nn) acc[oo][nn] = bv;
    }
    for (int kc = 0; kc < COUT; kc += KC){
        __syncthreads();
        for (int idx = tid; idx < KC * NT; idx += 256){
            const int k = idx / NT, n = idx % NT, c = kc + k;
            const float* src = (c < CIN) ? (x + ((size_t)b * CIN + c) * NTOK)
                                         : (xj + ((size_t)b * CIN + (c - CIN)) * NTOK);
            Xsm[k * NT + n] = src[nb + n];
        }
        __syncthreads();
        #pragma unroll 4
        for (int k = 0; k < KC; ++k){
            float a[4];
            #pragma unroll
            for (int oo = 0; oo < 4; ++oo) a[oo] = Wsm[(ty + 16 * oo) * COUT + kc + k];
            float bx[14];
            #pragma unroll
            for (int nn = 0; nn < 14; ++nn) bx[nn] = Xsm[k * NT + tx + 16 * nn];
            #pragma unroll
            for (int oo = 0; oo < 4; ++oo)
                #pragma unroll
                for (int nn = 0; nn < 14; ++nn)
                    acc[oo][nn] = fmaf(a[oo], bx[nn], acc[oo][nn]);
        }
    }
    float* yb = y + ((size_t)b * COUT + o0) * NTOK + nb;
    #pragma unroll
    for (int oo = 0; oo < 4; ++oo){
        const int o = ty + 16 * oo;
        float s1 = 0.0f, s2 = 0.0f;
        #pragma unroll
        for (int nn = 0; nn < 14; ++nn){
            const float v = acc[oo][nn];
            yb[(size_t)o * NTOK + tx + 16 * nn] = v;
            s1 += v; s2 += v * v;
        }
        #pragma unroll
        for (int off = 8; off > 0; off >>= 1){
            s1 += __shfl_xor_sync(0xffffffffu, s1, off, 16);
            s2 += __shfl_xor_sync(0xffffffffu, s2, off, 16);
        }
        if (tx == 0){ atomicAdd(&stats[o0 + o], s1); atomicAdd(&stats[COUT + o0 + o], s2); }
    }
}

__global__ void bn_gelu_kernel(const float* __restrict__ y, const float* __restrict__ stats,
                               const float* __restrict__ gamma, const float* __restrict__ beta,
                               float* __restrict__ out)
{
    const size_t idx = (size_t)blockIdx.x * blockDim.x + threadIdx.x;
    const int o = (int)((idx / NTOK) % COUT);
    const float invN = 1.0f / (float)NPOS;
    const float mean = stats[o] * invN;
    const float var  = stats[COUT + o] * invN - mean * mean;
    const float sc   = rsqrtf(var + 1e-5f);
    float v = (y[idx] - mean) * sc * gamma[o] + beta[o];
    out[idx] = 0.5f * v * (1.0f + erff(v * 0.70710678118654752f));
}

__global__ void zero_stats_kernel(float* stats){ stats[threadIdx.x] = 0.0f; }

// ---------------- launch ----------------
extern "C" void kernel_launch(void* const* d_in, const int* in_sizes, int n_in,
                              void* d_out, int out_size)
{
    const float* x      = (const float*)d_in[0];
    const float* conv_w = (const float*)d_in[1];
    const float* conv_b = (const float*)d_in[2];
    const float* gamma  = (const float*)d_in[3];
    const float* beta   = (const float*)d_in[4];
    float* out = (float*)d_out;

    float *xj, *y, *stats, *m;
    __nv_bfloat16 *kThi, *kTlo, *vhi, *vlo;
    cudaGetSymbolAddress((void**)&xj, d_xj);
    cudaGetSymbolAddress((void**)&y, d_y);
    cudaGetSymbolAddress((void**)&stats, d_stats);
    cudaGetSymbolAddress((void**)&m, d_m);
    cudaGetSymbolAddress((void**)&kThi, d_kThi);
    cudaGetSymbolAddress((void**)&kTlo, d_kTlo);
    cudaGetSymbolAddress((void**)&vhi, d_vhi);
    cudaGetSymbolAddress((void**)&vlo, d_vlo);

    const int conv_smem = (OT * COUT + KC * NT) * (int)sizeof(float);
    cudaFuncSetAttribute(attn_mma, cudaFuncAttributeMaxDynamicSharedMemorySize, ATT_SMEM);
    cudaFuncSetAttribute(conv_kernel, cudaFuncAttributeMaxDynamicSharedMemorySize, conv_smem);

    dim3 tgrid(NPAD / 32, CIN / 32, BATCH);
    prep_kT<<<tgrid, 256>>>(x, kThi, kTlo);
    prep_v<<<(BATCH * CIN * NTOK) / 256, 256>>>(x, vhi, vlo);
    dim3 mgrid((NTOK + 255) / 256, BATCH);
    prep_m<<<mgrid, 256>>>(x, m);
    zero_stats_kernel<<<1, 2 * COUT>>>(stats);

    dim3 agrid(NQB, BATCH);
    attn_mma<<<agrid, 256, ATT_SMEM>>>(x, xj, kThi, kTlo, vhi, vlo, m);

    dim3 cgrid(NTOK / NT, COUT / OT, BATCH);
    conv_kernel<<<cgrid, 256, conv_smem>>>(x, xj, conv_w, conv_b, y, stats);

    const size_t total = (size_t)BATCH * COUT * NTOK;
    bn_gelu_kernel<<<(unsigned)(total / 256), 256>>>(y, stats, gamma, beta, out);
}

// round 6
// speedup vs baseline: 6.5077x; 1.7159x over previous
#include <cuda_runtime.h>
#include <cuda_bf16.h>
#include <cstdint>
#include <math.h>

#define BATCH 8
#define CIN   96
#define COUT  192
#define NTOK  3136
#define NPOS  (BATCH * NTOK)
#define NPAD  3200

__device__ float d_y[BATCH * COUT * NTOK];
__device__ float d_stats[2 * COUT];
__device__ float d_m[BATCH * NTOK];
__device__ __nv_bfloat16 d_kThi[BATCH * NPAD * CIN];   // x as [b][tok][c]
__device__ __nv_bfloat16 d_kTlo[BATCH * NPAD * CIN];
__device__ __nv_bfloat16 d_vhi[BATCH * CIN * NTOK];    // x as [b][c][tok]
__device__ __nv_bfloat16 d_vlo[BATCH * CIN * NTOK];
__device__ __nv_bfloat16 d_xjThi[BATCH * NPAD * CIN];  // xj as [b][tok][c]
__device__ __nv_bfloat16 d_xjTlo[BATCH * NPAD * CIN];
__device__ __nv_bfloat16 d_whi[COUT * COUT];
__device__ __nv_bfloat16 d_wlo[COUT * COUT];

// ---------------- helpers ----------------
__device__ __forceinline__ uint32_t smem_u32(const void* p){
    uint32_t a;
    asm("{ .reg .u64 t; cvta.to.shared.u64 t, %1; cvt.u32.u64 %0, t; }" : "=r"(a) : "l"(p));
    return a;
}
__device__ __forceinline__ void ldsm4(uint32_t* r, uint32_t addr){
    asm volatile("ldmatrix.sync.aligned.m8n8.x4.shared.b16 {%0,%1,%2,%3}, [%4];"
        : "=r"(r[0]), "=r"(r[1]), "=r"(r[2]), "=r"(r[3]) : "r"(addr));
}
__device__ __forceinline__ void mma16816(float* d, const uint32_t* a, uint32_t b0, uint32_t b1){
    asm volatile("mma.sync.aligned.m16n8k16.row.col.f32.bf16.bf16.f32 "
        "{%0,%1,%2,%3}, {%4,%5,%6,%7}, {%8,%9}, {%0,%1,%2,%3};"
        : "+f"(d[0]), "+f"(d[1]), "+f"(d[2]), "+f"(d[3])
        : "r"(a[0]), "r"(a[1]), "r"(a[2]), "r"(a[3]), "r"(b0), "r"(b1));
}
__device__ __forceinline__ void split2(float f, __nv_bfloat16& h, __nv_bfloat16& lo){
    h  = __float2bfloat16(f);
    lo = __float2bfloat16(f - __bfloat162float(h));
}
__device__ __forceinline__ uint32_t packp(float a, float b){
    __nv_bfloat162 h = __floats2bfloat162_rn(a, b);
    return *reinterpret_cast<uint32_t*>(&h);
}
__device__ __forceinline__ uint32_t pack2h(__nv_bfloat16 a, __nv_bfloat16 b){
    __nv_bfloat162 h; h.x = a; h.y = b;
    return *reinterpret_cast<uint32_t*>(&h);
}
__device__ __forceinline__ void cpa16(uint32_t s, const void* g){
    unsigned long long ga = __cvta_generic_to_global(g);
    asm volatile("cp.async.cg.shared.global [%0], [%1], 16;" :: "r"(s), "l"(ga));
}
__device__ __forceinline__ void cpa_commit(){ asm volatile("cp.async.commit_group;"); }
__device__ __forceinline__ void cpa_wait0(){ asm volatile("cp.async.wait_group 0;" ::: "memory"); }
__device__ __forceinline__ void cpa_wait1(){ asm volatile("cp.async.wait_group 1;" ::: "memory"); }

// ---------------- prep kernels ----------------
__global__ void prep_kT(const float* __restrict__ x,
                        __nv_bfloat16* __restrict__ kThi, __nv_bfloat16* __restrict__ kTlo)
{
    __shared__ float tile[32][33];
    const int n0 = blockIdx.x * 32, c0 = blockIdx.y * 32, b = blockIdx.z;
    const float* xb = x + (size_t)b * CIN * NTOK;
    const int lane = threadIdx.x & 31, grp = threadIdx.x >> 5;
    #pragma unroll
    for (int i = 0; i < 4; ++i){
        const int c = i * 8 + grp, n = n0 + lane;
        tile[c][lane] = (n < NTOK) ? xb[(size_t)(c0 + c) * NTOK + n] : 0.0f;
    }
    __syncthreads();
    #pragma unroll
    for (int i = 0; i < 4; ++i){
        const int tok = i * 8 + grp, c = lane;
        __nv_bfloat16 h, lo;
        split2(tile[c][tok], h, lo);
        const size_t o = ((size_t)b * NPAD + n0 + tok) * CIN + c0 + c;
        kThi[o] = h; kTlo[o] = lo;
    }
}

__global__ void prep_v(const float* __restrict__ x,
                       __nv_bfloat16* __restrict__ vhi, __nv_bfloat16* __restrict__ vlo)
{
    const size_t i = (size_t)blockIdx.x * blockDim.x + threadIdx.x;
    __nv_bfloat16 h, lo;
    split2(x[i], h, lo);
    vhi[i] = h; vlo[i] = lo;
}

__global__ void prep_m(const float* __restrict__ x, float* __restrict__ m)
{
    const int n = blockIdx.x * 256 + threadIdx.x;
    const int b = blockIdx.y;
    if (n < NTOK){
        const float* xb = x + (size_t)b * CIN * NTOK + n;
        float s = 0.0f;
        #pragma unroll 8
        for (int c = 0; c < CIN; ++c){ float f = xb[(size_t)c * NTOK]; s = fmaf(f, f, s); }
        m[b * NTOK + n] = s;
    }
}

__global__ void prep_w(const float* __restrict__ w,
                       __nv_bfloat16* __restrict__ whi, __nv_bfloat16* __restrict__ wlo)
{
    const int i = blockIdx.x * 256 + threadIdx.x;   // 36864 total
    __nv_bfloat16 h, lo;
    split2(w[i], h, lo);
    whi[i] = h; wlo[i] = lo;
}

// zero xjT pad rows (tokens NTOK..NPAD-1) and stats
__global__ void zero_pad(__nv_bfloat16* __restrict__ xjThi, __nv_bfloat16* __restrict__ xjTlo,
                         float* __restrict__ stats)
{
    const int idx = blockIdx.x * 256 + threadIdx.x;   // 49152 total
    const int b = idx / ((NPAD - NTOK) * CIN);
    const int r = idx % ((NPAD - NTOK) * CIN);
    const size_t o = ((size_t)b * NPAD + NTOK) * CIN + r;
    xjThi[o] = __float2bfloat16(0.0f);
    xjTlo[o] = __float2bfloat16(0.0f);
    if (idx < 2 * COUT) stats[idx] = 0.0f;
}

// ---------------- attention ----------------
// smem: QHI 0 (26624, dead after preload -> KLO @0, Ost @0)
//       KHI0 26624, KHI1 39936 (13312 each)
//       QLO 53248 (26624, persistent)
//       VHI 79872, VLO 93696 (13824 each)
#define O_QHI  0
#define O_KLO  0
#define O_KHI0 26624
#define O_KHI1 39936
#define O_QLO  53248
#define O_VHI  79872
#define O_VLO  93696
#define ATT_SMEM 107520
#define NKT 49
#define NQB 25

__device__ __forceinline__ void issue_khi(uint32_t dst, const char* kThi, int t){
    const int n1 = t * 64;
    #pragma unroll
    for (int i = 0; i < 3; ++i){
        const int q = threadIdx.x + i * 256;
        const int row = q / 12, cb = q % 12;
        cpa16(dst + row * 208 + cb * 16, kThi + (size_t)(n1 + row) * 192 + cb * 16);
    }
}

__device__ __forceinline__ void gemm1_pass(float S[8][4], const uint32_t A[6][4], uint32_t kb){
    #pragma unroll
    for (int kk = 0; kk < 6; ++kk){
        #pragma unroll
        for (int g = 0; g < 4; ++g){
            uint32_t bb[4];
            ldsm4(bb, kb + (uint32_t)(g * 16 * 208 + kk * 32));
            mma16816(S[2 * g],     A[kk], bb[0], bb[2]);
            mma16816(S[2 * g + 1], A[kk], bb[1], bb[3]);
        }
    }
}
__device__ __forceinline__ void gemm2_pass(float O[12][4], const uint32_t A[4][4], uint32_t vb){
    #pragma unroll
    for (int kt = 0; kt < 4; ++kt){
        #pragma unroll
        for (int g = 0; g < 6; ++g){
            uint32_t bb[4];
            ldsm4(bb, vb + (uint32_t)(g * 16 * 144 + kt * 32));
            mma16816(O[2 * g],     A[kt], bb[0], bb[2]);
            mma16816(O[2 * g + 1], A[kt], bb[1], bb[3]);
        }
    }
}

__global__ __launch_bounds__(256, 2)
void attn_mma(const __nv_bfloat16* __restrict__ kThi_g, const __nv_bfloat16* __restrict__ kTlo_g,
              const __nv_bfloat16* __restrict__ vhi_g, const __nv_bfloat16* __restrict__ vlo_g,
              const float* __restrict__ m_g,
              __nv_bfloat16* __restrict__ xjThi_g, __nv_bfloat16* __restrict__ xjTlo_g)
{
    extern __shared__ char sm[];
    const int tid = threadIdx.x, w = tid >> 5, ln = tid & 31;
    const int b = blockIdx.y, n0 = blockIdx.x * 128;
    const uint32_t smb = smem_u32(sm);
    const char* kThi = (const char*)(kThi_g + (size_t)b * NPAD * CIN);
    const char* kTlo = (const char*)(kTlo_g + (size_t)b * NPAD * CIN);
    const char* vhi  = (const char*)(vhi_g + (size_t)b * CIN * NTOK);
    const char* vlo  = (const char*)(vlo_g + (size_t)b * CIN * NTOK);

    // group0: Q hi+lo
    #pragma unroll
    for (int i = 0; i < 6; ++i){
        const int q = tid + i * 256;
        const int row = q / 12, cb = q % 12;
        cpa16(smb + O_QHI + row * 208 + cb * 16, kThi + (size_t)(n0 + row) * 192 + cb * 16);
        cpa16(smb + O_QLO + row * 208 + cb * 16, kTlo + (size_t)(n0 + row) * 192 + cb * 16);
    }
    cpa_commit();
    // group1: khi tile0
    issue_khi(smb + O_KHI0, kThi, 0);
    cpa_commit();

    const int r0 = 16 * w + (ln >> 2), r1 = r0 + 8;
    const float M0 = (n0 + r0 < NTOK) ? m_g[b * NTOK + n0 + r0] : 3.0e38f;
    const float M1 = (n0 + r1 < NTOK) ? m_g[b * NTOK + n0 + r1] : 3.0e38f;

    cpa_wait1();           // Q ready
    __syncthreads();

    const int arow = ((ln >> 3) & 1) * 8 + (ln & 7);
    const int acol = (ln >> 4) * 8;
    uint32_t Qh[6][4];
    {
        const uint32_t aq = smb + O_QHI + (uint32_t)((16 * w + arow) * 208 + acol * 2);
        #pragma unroll
        for (int kk = 0; kk < 6; ++kk) ldsm4(Qh[kk], aq + kk * 32);
    }
    __syncthreads();       // QHI region now reusable

    float O[12][4];
    #pragma unroll
    for (int n = 0; n < 12; ++n){ O[n][0]=0.f; O[n][1]=0.f; O[n][2]=0.f; O[n][3]=0.f; }
    float L0 = 0.0f, L1 = 0.0f;

    for (int t = 0; t < NKT; ++t){
        if (t + 1 < NKT){
            issue_khi(smb + ((t + 1) & 1 ? O_KHI1 : O_KHI0), kThi, t + 1);
            cpa_commit();
            cpa_wait1();
        } else {
            cpa_wait0();
        }
        __syncthreads();

        const uint32_t kb = smb + (t & 1 ? O_KHI1 : O_KHI0) + (uint32_t)(arow * 208 + acol * 2);
        float S[8][4];
        #pragma unroll
        for (int n = 0; n < 8; ++n){ S[n][0]=0.f; S[n][1]=0.f; S[n][2]=0.f; S[n][3]=0.f; }
        gemm1_pass(S, Qh, kb);

        float mx = -3.0e38f;
        #pragma unroll
        for (int n = 0; n < 8; ++n){
            mx = fmaxf(mx, fmaxf(S[n][0], S[n][1]) - M0);
            mx = fmaxf(mx, fmaxf(S[n][2], S[n][3]) - M1);
        }
        const int need = __syncthreads_or(mx >= -19.0f);

        if (need){
            // lazy stage klo, vhi, vlo for current tile
            const int n1 = t * 64;
            #pragma unroll
            for (int i = 0; i < 3; ++i){
                const int q = tid + i * 256;
                const int row = q / 12, cb = q % 12;
                cpa16(smb + O_KLO + row * 208 + cb * 16, kTlo + (size_t)(n1 + row) * 192 + cb * 16);
            }
            #pragma unroll
            for (int i = 0; i < 3; ++i){
                const int q = tid + i * 256;
                const int c = q >> 3, cb = q & 7;
                cpa16(smb + O_VHI + c * 144 + cb * 16, vhi + ((size_t)c * NTOK + n1) * 2 + cb * 16);
                cpa16(smb + O_VLO + c * 144 + cb * 16, vlo + ((size_t)c * NTOK + n1) * 2 + cb * 16);
            }
            cpa_commit();
            cpa_wait0();
            __syncthreads();

            gemm1_pass(S, Qh, smb + O_KLO + (uint32_t)(arow * 208 + acol * 2));
            uint32_t Ql[6][4];
            {
                const uint32_t aq = smb + O_QLO + (uint32_t)((16 * w + arow) * 208 + acol * 2);
                #pragma unroll
                for (int kk = 0; kk < 6; ++kk) ldsm4(Ql[kk], aq + kk * 32);
            }
            gemm1_pass(S, Ql, kb);

            uint32_t Ph[4][4], Pl[4][4];
            #pragma unroll
            for (int n = 0; n < 8; ++n){
                const float p0 = __expf(S[n][0] - M0);
                const float p1 = __expf(S[n][1] - M0);
                const float p2 = __expf(S[n][2] - M1);
                const float p3 = __expf(S[n][3] - M1);
                L0 += p0 + p1;
                L1 += p2 + p3;
                const int kt = n >> 1, hh = (n & 1) * 2;
                Ph[kt][hh]     = packp(p0, p1);
                Ph[kt][hh + 1] = packp(p2, p3);
                const float q0 = p0 - __bfloat162float(__float2bfloat16(p0));
                const float q1 = p1 - __bfloat162float(__float2bfloat16(p1));
                const float q2 = p2 - __bfloat162float(__float2bfloat16(p2));
                const float q3 = p3 - __bfloat162float(__float2bfloat16(p3));
                Pl[kt][hh]     = packp(q0, q1);
                Pl[kt][hh + 1] = packp(q2, q3);
            }

            const uint32_t vb = smb + O_VHI + (uint32_t)(arow * 144 + acol * 2);
            gemm2_pass(O, Ph, vb);
            gemm2_pass(O, Ph, vb + (O_VLO - O_VHI));
            gemm2_pass(O, Pl, vb);
        }
        __syncthreads();
    }

    L0 += __shfl_xor_sync(0xffffffffu, L0, 1);
    L0 += __shfl_xor_sync(0xffffffffu, L0, 2);
    L1 += __shfl_xor_sync(0xffffffffu, L1, 1);
    L1 += __shfl_xor_sync(0xffffffffu, L1, 2);
    const float inv0 = 1.0f / L0, inv1 = 1.0f / L1;

    // stage O/l in smem as [tok][c] f32, stride 100
    float* Ost = (float*)sm;
    #pragma unroll
    for (int n = 0; n < 12; ++n){
        const int c = 8 * n + 2 * (ln & 3);
        Ost[r0 * 100 + c]     = O[n][0] * inv0;
        Ost[r0 * 100 + c + 1] = O[n][1] * inv0;
        Ost[r1 * 100 + c]     = O[n][2] * inv1;
        Ost[r1 * 100 + c + 1] = O[n][3] * inv1;
    }
    __syncthreads();

    // xjT = relu(x~ - O/l), split to bf16 hi/lo, [tok][c]
    char* xjThi = (char*)(xjThi_g + (size_t)b * NPAD * CIN);
    char* xjTlo = (char*)(xjTlo_g + (size_t)b * NPAD * CIN);
    for (int idx = tid; idx < 128 * 48; idx += 256){
        const int row = idx / 48, cp = idx % 48;
        const int nq = n0 + row;
        if (nq < NTOK){
            const uint32_t hp = *(const uint32_t*)(kThi + (size_t)nq * 192 + cp * 4);
            const uint32_t lp = *(const uint32_t*)(kTlo + (size_t)nq * 192 + cp * 4);
            const __nv_bfloat162 hb = *reinterpret_cast<const __nv_bfloat162*>(&hp);
            const __nv_bfloat162 lb = *reinterpret_cast<const __nv_bfloat162*>(&lp);
            const float x0 = __bfloat162float(hb.x) + __bfloat162float(lb.x);
            const float x1 = __bfloat162float(hb.y) + __bfloat162float(lb.y);
            const float v0 = fmaxf(x0 - Ost[row * 100 + 2 * cp], 0.0f);
            const float v1 = fmaxf(x1 - Ost[row * 100 + 2 * cp + 1], 0.0f);
            __nv_bfloat16 h0, l0, h1, l1;
            split2(v0, h0, l0); split2(v1, h1, l1);
            *(uint32_t*)(xjThi + (size_t)nq * 192 + cp * 4) = pack2h(h0, h1);
            *(uint32_t*)(xjTlo + (size_t)nq * 192 + cp * 4) = pack2h(l0, l1);
        }
    }
}

// ---------------- conv via mma (3-pass bf16 split) ----------------
// CTA: 96 out-channels x 128 tokens, 384 threads (12 warps: mb=w>>1, nh=w&1)
// smem: Whi 0 (38400), Wlo 38400, Xhi 76800 (51200), Xlo 128000 -> 179200
#define CV_SMEM 179200
__global__ __launch_bounds__(384, 1)
void conv_mma(const __nv_bfloat16* __restrict__ whi_g, const __nv_bfloat16* __restrict__ wlo_g,
              const __nv_bfloat16* __restrict__ kThi_g, const __nv_bfloat16* __restrict__ kTlo_g,
              const __nv_bfloat16* __restrict__ xjThi_g, const __nv_bfloat16* __restrict__ xjTlo_g,
              const float* __restrict__ bias, float* __restrict__ y, float* __restrict__ stats)
{
    extern __shared__ char sm[];
    const int tid = threadIdx.x, w = tid >> 5, ln = tid & 31;
    const int n0 = blockIdx.x * 128, o0 = blockIdx.y * 96, b = blockIdx.z;
    const uint32_t smb = smem_u32(sm);
    const char* whi = (const char*)whi_g;
    const char* wlo = (const char*)wlo_g;
    const char* kThi = (const char*)(kThi_g + (size_t)b * NPAD * CIN);
    const char* kTlo = (const char*)(kTlo_g + (size_t)b * NPAD * CIN);
    const char* xjThi = (const char*)(xjThi_g + (size_t)b * NPAD * CIN);
    const char* xjTlo = (const char*)(xjTlo_g + (size_t)b * NPAD * CIN);

    // stage W (96 rows x 384B, hi+lo)
    #pragma unroll
    for (int i = 0; i < 12; ++i){
        const int q = tid + i * 384;          // 0..4607
        const int sel = q / 2304, r = q % 2304;
        const int row = r / 24, cb = r % 24;
        const char* src = (sel ? wlo : whi) + (size_t)(o0 + row) * 384 + cb * 16;
        cpa16(smb + sel * 38400 + row * 400 + cb * 16, src);
    }
    // stage X rows n0..n0+127: [n][k], k<96 from x(kT), k>=96 from xjT
    #pragma unroll
    for (int i = 0; i < 16; ++i){
        const int q = tid + i * 384;          // 0..6143
        const int sel = q / 3072, r = q % 3072;
        const int row = r / 24, cb = r % 24;
        const char* src;
        if (cb < 12) src = (sel ? kTlo : kThi) + (size_t)(n0 + row) * 192 + cb * 16;
        else         src = (sel ? xjTlo : xjThi) + (size_t)(n0 + row) * 192 + (cb - 12) * 16;
        cpa16(smb + 76800 + sel * 51200 + row * 400 + cb * 16, src);
    }
    cpa_commit();
    cpa_wait0();
    __syncthreads();

    const int mb = w >> 1, nh = w & 1;
    const int arow = ((ln >> 3) & 1) * 8 + (ln & 7);
    const int acol = (ln >> 4) * 8;
    const uint32_t Wh = smb + (uint32_t)((mb * 16 + arow) * 400 + acol * 2);
    const uint32_t Wl = Wh + 38400;
    const uint32_t Xh = smb + 76800 + (uint32_t)((nh * 64 + arow) * 400 + acol * 2);
    const uint32_t Xl = Xh + 51200;

    float acc[8][4];
    #pragma unroll
    for (int k = 0; k < 8; ++k){ acc[k][0]=0.f; acc[k][1]=0.f; acc[k][2]=0.f; acc[k][3]=0.f; }

    #pragma unroll
    for (int ks = 0; ks < 12; ++ks){
        uint32_t Ah[4], Al[4];
        ldsm4(Ah, Wh + ks * 32);
        ldsm4(Al, Wl + ks * 32);
        #pragma unroll
        for (int g = 0; g < 4; ++g){
            uint32_t Bh[4], Bl[4];
            ldsm4(Bh, Xh + (uint32_t)(g * 16 * 400 + ks * 32));
            ldsm4(Bl, Xl + (uint32_t)(g * 16 * 400 + ks * 32));
            mma16816(acc[2 * g],     Ah, Bh[0], Bh[2]);
            mma16816(acc[2 * g + 1], Ah, Bh[1], Bh[3]);
            mma16816(acc[2 * g],     Ah, Bl[0], Bl[2]);
            mma16816(acc[2 * g + 1], Ah, Bl[1], Bl[3]);
            mma16816(acc[2 * g],     Al, Bh[0], Bh[2]);
            mma16816(acc[2 * g + 1], Al, Bh[1], Bh[3]);
        }
    }

    // epilogue: add bias, store y, accumulate stats
    const int r0 = o0 + mb * 16 + (ln >> 2), r1 = r0 + 8;
    const float b0 = bias[r0], b1 = bias[r1];
    float* yb = y + (size_t)b * COUT * NTOK;
    float s10 = 0.f, s20 = 0.f, s11 = 0.f, s21 = 0.f;
    #pragma unroll
    for (int k = 0; k < 8; ++k){
        const int n = n0 + nh * 64 + (k >> 1) * 16 + (k & 1) * 8 + (ln & 3) * 2;
        if (n < NTOK){
            const float v0 = acc[k][0] + b0, v1 = acc[k][1] + b0;
            const float v2 = acc[k][2] + b1, v3 = acc[k][3] + b1;
            float2 p0; p0.x = v0; p0.y = v1;
            float2 p1; p1.x = v2; p1.y = v3;
            *(float2*)&yb[(size_t)r0 * NTOK + n] = p0;
            *(float2*)&yb[(size_t)r1 * NTOK + n] = p1;
            s10 += v0 + v1; s20 += v0 * v0 + v1 * v1;
            s11 += v2 + v3; s21 += v2 * v2 + v3 * v3;
        }
    }
    #pragma unroll
    for (int off = 1; off <= 2; off <<= 1){
        s10 += __shfl_xor_sync(0xffffffffu, s10, off);
        s20 += __shfl_xor_sync(0xffffffffu, s20, off);
        s11 += __shfl_xor_sync(0xffffffffu, s11, off);
        s21 += __shfl_xor_sync(0xffffffffu, s21, off);
    }
    if ((ln & 3) == 0){
        atomicAdd(&stats[r0], s10); atomicAdd(&stats[COUT + r0], s20);
        atomicAdd(&stats[r1], s11); atomicAdd(&stats[COUT + r1], s21);
    }
}

// ---------------- BN + GELU (float4) ----------------
__global__ void bn_gelu4(const float4* __restrict__ y4, const float* __restrict__ stats,
                         const float* __restrict__ gamma, const float* __restrict__ beta,
                         float4* __restrict__ out4)
{
    const size_t idx = (size_t)blockIdx.x * 256 + threadIdx.x;
    const int o = (int)((idx * 4) / NTOK) % COUT;
    const float invN = 1.0f / (float)NPOS;
    const float mean = stats[o] * invN;
    const float var  = stats[COUT + o] * invN - mean * mean;
    const float sc   = rsqrtf(var + 1e-5f) * gamma[o];
    const float be   = beta[o];
    float4 v = y4[idx];
    float a0 = (v.x - mean) * sc + be;
    float a1 = (v.y - mean) * sc + be;
    float a2 = (v.z - mean) * sc + be;
    float a3 = (v.w - mean) * sc + be;
    v.x = 0.5f * a0 * (1.0f + erff(a0 * 0.70710678118654752f));
    v.y = 0.5f * a1 * (1.0f + erff(a1 * 0.70710678118654752f));
    v.z = 0.5f * a2 * (1.0f + erff(a2 * 0.70710678118654752f));
    v.w = 0.5f * a3 * (1.0f + erff(a3 * 0.70710678118654752f));
    out4[idx] = v;
}

// ---------------- launch ----------------
extern "C" void kernel_launch(void* const* d_in, const int* in_sizes, int n_in,
                              void* d_out, int out_size)
{
    const float* x      = (const float*)d_in[0];
    const float* conv_w = (const float*)d_in[1];
    const float* conv_b = (const float*)d_in[2];
    const float* gamma  = (const float*)d_in[3];
    const float* beta   = (const float*)d_in[4];
    float* out = (float*)d_out;

    float *y, *stats, *m;
    __nv_bfloat16 *kThi, *kTlo, *vhi, *vlo, *xjThi, *xjTlo, *whi, *wlo;
    cudaGetSymbolAddress((void**)&y, d_y);
    cudaGetSymbolAddress((void**)&stats, d_stats);
    cudaGetSymbolAddress((void**)&m, d_m);
    cudaGetSymbolAddress((void**)&kThi, d_kThi);
    cudaGetSymbolAddress((void**)&kTlo, d_kTlo);
    cudaGetSymbolAddress((void**)&vhi, d_vhi);
    cudaGetSymbolAddress((void**)&vlo, d_vlo);
    cudaGetSymbolAddress((void**)&xjThi, d_xjThi);
    cudaGetSymbolAddress((void**)&xjTlo, d_xjTlo);
    cudaGetSymbolAddress((void**)&whi, d_whi);
    cudaGetSymbolAddress((void**)&wlo, d_wlo);

    cudaFuncSetAttribute(attn_mma, cudaFuncAttributeMaxDynamicSharedMemorySize, ATT_SMEM);
    cudaFuncSetAttribute(conv_mma, cudaFuncAttributeMaxDynamicSharedMemorySize, CV_SMEM);

    dim3 tgrid(NPAD / 32, CIN / 32, BATCH);
    prep_kT<<<tgrid, 256>>>(x, kThi, kTlo);
    prep_v<<<(BATCH * CIN * NTOK) / 256, 256>>>(x, vhi, vlo);
    dim3 mgrid((NTOK + 255) / 256, BATCH);
    prep_m<<<mgrid, 256>>>(x, m);
    prep_w<<<(COUT * COUT) / 256, 256>>>(conv_w, whi, wlo);
    zero_pad<<<(BATCH * (NPAD - NTOK) * CIN) / 256, 256>>>(xjThi, xjTlo, stats);

    dim3 agrid(NQB, BATCH);
    attn_mma<<<agrid, 256, ATT_SMEM>>>(kThi, kTlo, vhi, vlo, m, xjThi, xjTlo);

    dim3 cgrid(NQB, 2, BATCH);
    conv_mma<<<cgrid, 384, CV_SMEM>>>(whi, wlo, kThi, kTlo, xjThi, xjTlo, conv_b, y, stats);

    bn_gelu4<<<(unsigned)((size_t)BATCH * COUT * NTOK / 4 / 256), 256>>>(
        (const float4*)y, stats, gamma, beta, (float4*)out);
}